// round 8
// baseline (speedup 1.0000x reference)
#include <cuda_runtime.h>
#include <cuda_fp16.h>
#include <cstdint>
#include <math.h>

#define NE   8
#define HD   2048
#define ID   1024
#define NT   8192
#define TOPK 2
#define MAXP (NT * TOPK)

// smem geometry (fp16 elems)
#define SAW    72                   // A row stride: 32 data + 40 pad (144 B, 16B-mult, bank step 4)
#define SBW    136                  // B row stride: 128 data + 8 pad (272 B, 16B-mult, bank step 4)
#define ABYTES (128 * SAW * 2)      // 18432 per (hi or lo)
#define BOFF   (2 * ABYTES)         // 36864
#define BBYTES (32 * SBW * 2)       // 8704
#define STAGE  (BOFF + BBYTES)      // 45568
#define SMEM_SZ (3 * STAGE)         // 136704

// ---- device globals ----
__device__ int    g_cnt[NE];
__device__ int    g_pair[NE * MAXP];
__device__ __half g_x_h[(size_t)NT * HD];
__device__ __half g_x_l[(size_t)NT * HD];
__device__ __half g_gw[(size_t)NE * HD * ID];
__device__ __half g_uw[(size_t)NE * HD * ID];
__device__ __half g_dw[(size_t)NE * ID * HD];
__device__ __half g_act_h[(size_t)MAXP * ID];
__device__ __half g_act_l[(size_t)MAXP * ID];
__device__ float  g_ds[(size_t)MAXP * HD];

// ============================ asm helpers ============================
__device__ __forceinline__ uint32_t smem_to_u32(const void* p) {
    uint32_t a;
    asm("{ .reg .u64 t; cvta.to.shared.u64 t, %1; cvt.u32.u64 %0, t; }" : "=r"(a) : "l"(p));
    return a;
}
__device__ __forceinline__ void ldm_x4(uint32_t* r, uint32_t a) {
    asm volatile("ldmatrix.sync.aligned.m8n8.x4.shared.b16 {%0,%1,%2,%3}, [%4];"
                 : "=r"(r[0]), "=r"(r[1]), "=r"(r[2]), "=r"(r[3]) : "r"(a));
}
__device__ __forceinline__ void ldm_x4_t(uint32_t* r, uint32_t a) {
    asm volatile("ldmatrix.sync.aligned.m8n8.x4.trans.shared.b16 {%0,%1,%2,%3}, [%4];"
                 : "=r"(r[0]), "=r"(r[1]), "=r"(r[2]), "=r"(r[3]) : "r"(a));
}
__device__ __forceinline__ void mma16816(float* c, const uint32_t* a, uint32_t b0, uint32_t b1) {
    asm volatile("mma.sync.aligned.m16n8k16.row.col.f32.f16.f16.f32 "
                 "{%0,%1,%2,%3}, {%4,%5,%6,%7}, {%8,%9}, {%0,%1,%2,%3};"
                 : "+f"(c[0]), "+f"(c[1]), "+f"(c[2]), "+f"(c[3])
                 : "r"(a[0]), "r"(a[1]), "r"(a[2]), "r"(a[3]), "r"(b0), "r"(b1));
}
#define CP16(dst, src) \
    asm volatile("cp.async.cg.shared.global [%0], [%1], 16;" :: "r"(dst), "l"(src) : "memory")
#define CP16Z(dst, src, n) \
    asm volatile("cp.async.cg.shared.global [%0], [%1], 16, %2;" :: "r"(dst), "l"(src), "r"(n) : "memory")
#define CP_COMMIT() asm volatile("cp.async.commit_group;" ::: "memory")
#define CP_WAIT1()  asm volatile("cp.async.wait_group 1;" ::: "memory")
#define CP_WAIT0()  asm volatile("cp.async.wait_group 0;" ::: "memory")

__device__ __forceinline__ float gelu_tanh(float gv) {
    float t  = gv + 0.044715f * gv * gv * gv;
    float z  = 1.5957691216057308f * t;
    float th = 1.0f - 2.0f / (__expf(z) + 1.0f);
    return 0.5f * gv * (1.0f + th);
}
__device__ __forceinline__ uint32_t pkh(__half a, __half b) {
    __half2 t = __halves2half2(a, b);
    return *reinterpret_cast<uint32_t*>(&t);
}

// ============================ prep kernels ============================
__global__ void k_zero_counts() { if (threadIdx.x < NE) g_cnt[threadIdx.x] = 0; }

__global__ void k_route(const int* __restrict__ sel) {
    int p = blockIdx.x * blockDim.x + threadIdx.x;
    if (p < MAXP) {
        int e = sel[p];
        int pos = atomicAdd(&g_cnt[e], 1);
        g_pair[e * MAXP + pos] = p;
    }
}

// fp32 -> fp16 (round-to-nearest), vectorized x4
__global__ void k_half4(const float* __restrict__ src, __half* __restrict__ dst, int n4) {
    int i = blockIdx.x * blockDim.x + threadIdx.x;
    if (i >= n4) return;
    float4 v = ((const float4*)src)[i];
    __half2 a = __floats2half2_rn(v.x, v.y);
    __half2 b = __floats2half2_rn(v.z, v.w);
    ((uint2*)dst)[i] = make_uint2(*(uint32_t*)&a, *(uint32_t*)&b);
}

// fp32 -> fp16 hi + fp16 lo residual
__global__ void k_split4(const float* __restrict__ src,
                         __half* __restrict__ dh, __half* __restrict__ dl, int n4) {
    int i = blockIdx.x * blockDim.x + threadIdx.x;
    if (i >= n4) return;
    float4 v = ((const float4*)src)[i];
    __half h0 = __float2half_rn(v.x), h1 = __float2half_rn(v.y);
    __half h2 = __float2half_rn(v.z), h3 = __float2half_rn(v.w);
    __half l0 = __float2half_rn(v.x - __half2float(h0));
    __half l1 = __float2half_rn(v.y - __half2float(h1));
    __half l2 = __float2half_rn(v.z - __half2float(h2));
    __half l3 = __float2half_rn(v.w - __half2float(h3));
    ((uint2*)dh)[i] = make_uint2(pkh(h0, h1), pkh(h2, h3));
    ((uint2*)dl)[i] = make_uint2(pkh(l0, l1), pkh(l2, l3));
}

// ============================ issue helpers ============================
// A tile: 128 rows x 32 k, hi+lo (gathered). 2 cp.async/thread.
// B tile: 32 k x 128 n, single fp16.   1 cp.async/thread.
__device__ __forceinline__ void gu_issue(int ck, int st, uint32_t sbd, const int* sPair,
                                         const __half* gw, const __half* uw,
                                         int cb, int tid)
{
    uint32_t sbase = sbd + st * STAGE;
    #pragma unroll
    for (int it = 0; it < 2; ++it) {
        int s = tid + it * 512;
        int hl = s >> 9, rem = s & 511;
        int r = rem >> 2, c = rem & 3;
        int pr = sPair[r];
        const __half* src = (hl ? g_x_l : g_x_h)
                          + ((size_t)((pr >= 0) ? (pr >> 1) : 0) * HD + ck * 32 + c * 8);
        uint32_t dst = sbase + hl * ABYTES + (uint32_t)(r * SAW + c * 8) * 2;
        CP16Z(dst, src, (pr >= 0) ? 16u : 0u);
    }
    {
        int r = tid >> 4, c = tid & 15;           // c: 0..7 gate, 8..15 up
        const __half* w = (c < 8) ? gw : uw;
        const __half* src = w + (size_t)(ck * 32 + r) * ID + cb * 64 + (c & 7) * 8;
        uint32_t dst = sbase + BOFF + (uint32_t)(r * SBW + c * 8) * 2;
        CP16(dst, src);
    }
    CP_COMMIT();
}

__device__ __forceinline__ void dn_issue(int ck, int st, uint32_t sbd, const int* sPair,
                                         const __half* dw, int cb, int tid)
{
    uint32_t sbase = sbd + st * STAGE;
    #pragma unroll
    for (int it = 0; it < 2; ++it) {
        int s = tid + it * 512;
        int hl = s >> 9, rem = s & 511;
        int r = rem >> 2, c = rem & 3;
        int pr = sPair[r];
        const __half* src = (hl ? g_act_l : g_act_h)
                          + ((size_t)((pr >= 0) ? pr : 0) * ID + ck * 32 + c * 8);
        uint32_t dst = sbase + hl * ABYTES + (uint32_t)(r * SAW + c * 8) * 2;
        CP16Z(dst, src, (pr >= 0) ? 16u : 0u);
    }
    {
        int r = tid >> 4, c = tid & 15;
        const __half* src = dw + (size_t)(ck * 32 + r) * HD + cb * 128 + c * 8;
        uint32_t dst = sbase + BOFF + (uint32_t)(r * SBW + c * 8) * 2;
        CP16(dst, src);
    }
    CP_COMMIT();
}

// ============================ gate+up ============================
// CTA: 128 pairs x (64 gate + 64 up cols), K=HD, 32-chunks, 3-stage cp.async.
__global__ __launch_bounds__(512, 1)
void k_gateup(const float* __restrict__ rw)
{
    const int e = blockIdx.z;
    const int cnt = g_cnt[e];
    const int row0 = blockIdx.y * 128;
    if (row0 >= cnt) return;
    const int cb = blockIdx.x;

    extern __shared__ char smem[];
    __shared__ int sPair[128];
    const uint32_t sbd = smem_to_u32(smem);
    const int tid = threadIdx.x, wid = tid >> 5, lane = tid & 31;
    const int wm = wid >> 2, wn = wid & 3;

    if (tid < 128) {
        int pos = row0 + tid;
        sPair[tid] = (pos < cnt) ? g_pair[e * MAXP + pos] : -1;
    }
    __syncthreads();

    const __half* gw = g_gw + (size_t)e * HD * ID;
    const __half* uw = g_uw + (size_t)e * HD * ID;

    float acc[2][2][2][4];
    #pragma unroll
    for (int i = 0; i < 2; ++i)
        #pragma unroll
        for (int j = 0; j < 2; ++j)
            #pragma unroll
            for (int s = 0; s < 2; ++s)
                #pragma unroll
                for (int q = 0; q < 4; ++q) acc[i][j][s][q] = 0.f;

    gu_issue(0, 0, sbd, sPair, gw, uw, cb, tid);
    gu_issue(1, 1, sbd, sPair, gw, uw, cb, tid);

    const int NCK = HD / 32;
    for (int ck = 0; ck < NCK; ++ck) {
        if (ck < NCK - 1) CP_WAIT1(); else CP_WAIT0();
        __syncthreads();

        const int st = ck % 3;
        uint32_t uA = sbd + st * STAGE;
        uint32_t uB = uA + BOFF;
        #pragma unroll
        for (int ks = 0; ks < 2; ++ks) {
            uint32_t ah[2][4], al[2][4];
            #pragma unroll
            for (int mt = 0; mt < 2; ++mt) {
                uint32_t off = (uint32_t)((wm * 32 + mt * 16 + (lane & 15)) * SAW
                                          + ks * 16 + ((lane >> 4) << 3)) * 2;
                ldm_x4(ah[mt], uA + off);
                ldm_x4(al[mt], uA + ABYTES + off);
            }
            uint32_t bg[4], bu[4];
            uint32_t brow = (uint32_t)(ks * 16 + (lane & 15));
            uint32_t co   = (uint32_t)((lane >> 4) << 3);
            ldm_x4_t(bg, uB + (brow * SBW + wn * 16 + co) * 2);
            ldm_x4_t(bu, uB + (brow * SBW + 64 + wn * 16 + co) * 2);
            #pragma unroll
            for (int mt = 0; mt < 2; ++mt)
                #pragma unroll
                for (int s = 0; s < 2; ++s) {
                    mma16816(acc[mt][0][s], ah[mt], bg[2 * s], bg[2 * s + 1]);
                    mma16816(acc[mt][0][s], al[mt], bg[2 * s], bg[2 * s + 1]);
                    mma16816(acc[mt][1][s], ah[mt], bu[2 * s], bu[2 * s + 1]);
                    mma16816(acc[mt][1][s], al[mt], bu[2 * s], bu[2 * s + 1]);
                }
        }
        if (ck + 2 < NCK) gu_issue(ck + 2, (ck + 2) % 3, sbd, sPair, gw, uw, cb, tid);
    }

    // epilogue: act = rw * gelu(gate) * up -> fp16 hi/lo scratch
    #pragma unroll
    for (int mt = 0; mt < 2; ++mt)
        #pragma unroll
        for (int s = 0; s < 2; ++s) {
            int c = cb * 64 + wn * 16 + s * 8 + (lane & 3) * 2;
            #pragma unroll
            for (int half = 0; half < 2; ++half) {
                int r = wm * 32 + mt * 16 + (lane >> 2) + half * 8;
                int pr = sPair[r];
                if (pr < 0) continue;
                float wgt = rw[pr];
                float g0 = acc[mt][0][s][half * 2], g1 = acc[mt][0][s][half * 2 + 1];
                float u0 = acc[mt][1][s][half * 2], u1 = acc[mt][1][s][half * 2 + 1];
                float o0 = wgt * gelu_tanh(g0) * u0;
                float o1 = wgt * gelu_tanh(g1) * u1;
                __half h0 = __float2half_rn(o0), h1 = __float2half_rn(o1);
                __half l0 = __float2half_rn(o0 - __half2float(h0));
                __half l1 = __float2half_rn(o1 - __half2float(h1));
                size_t base = (size_t)pr * ID + c;
                *(uint32_t*)(g_act_h + base) = pkh(h0, h1);
                *(uint32_t*)(g_act_l + base) = pkh(l0, l1);
            }
        }
}

// ============================ down ============================
// CTA: 128 pairs x 128 hidden cols, K=ID, 32-chunks, 3-stage cp.async.
__global__ __launch_bounds__(512, 1)
void k_down()
{
    const int e = blockIdx.z;
    const int cnt = g_cnt[e];
    const int row0 = blockIdx.y * 128;
    if (row0 >= cnt) return;
    const int cb = blockIdx.x;

    extern __shared__ char smem[];
    __shared__ int sPair[128];
    const uint32_t sbd = smem_to_u32(smem);
    const int tid = threadIdx.x, wid = tid >> 5, lane = tid & 31;
    const int wm = wid >> 2, wn = wid & 3;

    if (tid < 128) {
        int pos = row0 + tid;
        sPair[tid] = (pos < cnt) ? g_pair[e * MAXP + pos] : -1;
    }
    __syncthreads();

    const __half* dw = g_dw + (size_t)e * ID * HD;

    float acc[2][4][4];
    #pragma unroll
    for (int i = 0; i < 2; ++i)
        #pragma unroll
        for (int j = 0; j < 4; ++j)
            #pragma unroll
            for (int q = 0; q < 4; ++q) acc[i][j][q] = 0.f;

    dn_issue(0, 0, sbd, sPair, dw, cb, tid);
    dn_issue(1, 1, sbd, sPair, dw, cb, tid);

    const int NCK = ID / 32;
    for (int ck = 0; ck < NCK; ++ck) {
        if (ck < NCK - 1) CP_WAIT1(); else CP_WAIT0();
        __syncthreads();

        const int st = ck % 3;
        uint32_t uA = sbd + st * STAGE;
        uint32_t uB = uA + BOFF;
        #pragma unroll
        for (int ks = 0; ks < 2; ++ks) {
            uint32_t ah[2][4], al[2][4];
            #pragma unroll
            for (int mt = 0; mt < 2; ++mt) {
                uint32_t off = (uint32_t)((wm * 32 + mt * 16 + (lane & 15)) * SAW
                                          + ks * 16 + ((lane >> 4) << 3)) * 2;
                ldm_x4(ah[mt], uA + off);
                ldm_x4(al[mt], uA + ABYTES + off);
            }
            uint32_t bh[2][4];
            uint32_t brow = (uint32_t)(ks * 16 + (lane & 15));
            uint32_t co   = (uint32_t)((lane >> 4) << 3);
            #pragma unroll
            for (int np = 0; np < 2; ++np)
                ldm_x4_t(bh[np], uB + (brow * SBW + wn * 32 + np * 16 + co) * 2);
            #pragma unroll
            for (int mt = 0; mt < 2; ++mt)
                #pragma unroll
                for (int np = 0; np < 2; ++np)
                    #pragma unroll
                    for (int s = 0; s < 2; ++s) {
                        int j = np * 2 + s;
                        mma16816(acc[mt][j], ah[mt], bh[np][2 * s], bh[np][2 * s + 1]);
                        mma16816(acc[mt][j], al[mt], bh[np][2 * s], bh[np][2 * s + 1]);
                    }
        }
        if (ck + 2 < NCK) dn_issue(ck + 2, (ck + 2) % 3, sbd, sPair, dw, cb, tid);
    }

    // epilogue: per-pair fp32 scratch
    #pragma unroll
    for (int mt = 0; mt < 2; ++mt)
        #pragma unroll
        for (int j = 0; j < 4; ++j) {
            int c = cb * 128 + wn * 32 + j * 8 + (lane & 3) * 2;
            #pragma unroll
            for (int half = 0; half < 2; ++half) {
                int r = wm * 32 + mt * 16 + (lane >> 2) + half * 8;
                int pr = sPair[r];
                if (pr < 0) continue;
                float2 v = make_float2(acc[mt][j][half * 2], acc[mt][j][half * 2 + 1]);
                *(float2*)(g_ds + (size_t)pr * HD + c) = v;
            }
        }
}

// ============================ combine ============================
__global__ void k_combine(float* __restrict__ out) {
    int idx = blockIdx.x * blockDim.x + threadIdx.x;
    int t  = idx >> 9;
    int c4 = idx & 511;
    const float4* s4 = (const float4*)g_ds;
    float4 a = s4[(size_t)(2 * t) * 512 + c4];
    float4 b = s4[(size_t)(2 * t + 1) * 512 + c4];
    ((float4*)out)[idx] = make_float4(a.x + b.x, a.y + b.y, a.z + b.z, a.w + b.w);
}

// ============================ host ============================
extern "C" void kernel_launch(void* const* d_in, const int* in_sizes, int n_in,
                              void* d_out, int out_size)
{
    const float* x      = (const float*)d_in[0];
    const int*   sel    = (const int*)  d_in[1];
    const float* rw     = (const float*)d_in[2];
    const float* gate_w = (const float*)d_in[3];
    const float* up_w   = (const float*)d_in[4];
    const float* down_w = (const float*)d_in[5];
    float* out = (float*)d_out;

    cudaFuncSetAttribute(k_gateup, cudaFuncAttributeMaxDynamicSharedMemorySize, SMEM_SZ);
    cudaFuncSetAttribute(k_down,   cudaFuncAttributeMaxDynamicSharedMemorySize, SMEM_SZ);

    k_zero_counts<<<1, 32>>>();
    k_route<<<MAXP / 256, 256>>>(sel);

    // pre-split x; pre-round weights to fp16
    {
        __half *xh, *xl, *gw, *uw, *dww;
        cudaGetSymbolAddress((void**)&xh,  g_x_h);
        cudaGetSymbolAddress((void**)&xl,  g_x_l);
        cudaGetSymbolAddress((void**)&gw,  g_gw);
        cudaGetSymbolAddress((void**)&uw,  g_uw);
        cudaGetSymbolAddress((void**)&dww, g_dw);
        int nx4 = NT * HD / 4;
        int nw4 = NE * HD * ID / 4;
        k_split4<<<(nx4 + 255) / 256, 256>>>(x, xh, xl, nx4);
        k_half4<<<(nw4 + 255) / 256, 256>>>(gate_w, gw, nw4);
        k_half4<<<(nw4 + 255) / 256, 256>>>(up_w,   uw, nw4);
        k_half4<<<(nw4 + 255) / 256, 256>>>(down_w, dww, nw4);
    }

    dim3 g1(ID / 64, MAXP / 128, NE);    // 16 x 128 x 8
    k_gateup<<<g1, 512, SMEM_SZ>>>(rw);

    dim3 g2(HD / 128, MAXP / 128, NE);   // 16 x 128 x 8
    k_down<<<g2, 512, SMEM_SZ>>>();

    k_combine<<<(NT * HD / 4) / 256, 256>>>(out);
}

// round 10
// speedup vs baseline: 1.8049x; 1.8049x over previous
#include <cuda_runtime.h>
#include <cuda_fp16.h>
#include <cstdint>
#include <math.h>

#define NE   8
#define HD   2048
#define ID   1024
#define NT   8192
#define TOPK 2
#define MAXP (NT * TOPK)

// smem geometry (fp16 elems)
#define SAW    40                   // A row stride: 32 data + 8 pad (80 B: 16B-mult, 20-bank step)
#define SBW    136                  // B row stride: 128 data + 8 pad (272 B: 16B-mult, 4-bank step)
#define ABYTES (128 * SAW * 2)      // 10240 per (hi or lo)
#define BOFF   (2 * ABYTES)         // 20480
#define BBYTES (32 * SBW * 2)       // 8704
#define STAGE  (BOFF + BBYTES)      // 29184
#define SMEM_SZ (3 * STAGE)         // 87552  -> 2 CTAs/SM

// ---- device globals ----
__device__ int    g_cnt[NE];
__device__ int    g_pair[NE * MAXP];
__device__ __half g_x_h[(size_t)NT * HD];
__device__ __half g_x_l[(size_t)NT * HD];
__device__ __half g_gw[(size_t)NE * HD * ID];
__device__ __half g_uw[(size_t)NE * HD * ID];
__device__ __half g_dw[(size_t)NE * ID * HD];
__device__ __half g_act_h[(size_t)MAXP * ID];
__device__ __half g_act_l[(size_t)MAXP * ID];
__device__ float  g_ds[(size_t)MAXP * HD];

// ============================ asm helpers ============================
__device__ __forceinline__ uint32_t smem_to_u32(const void* p) {
    uint32_t a;
    asm("{ .reg .u64 t; cvta.to.shared.u64 t, %1; cvt.u32.u64 %0, t; }" : "=r"(a) : "l"(p));
    return a;
}
__device__ __forceinline__ void ldm_x4(uint32_t* r, uint32_t a) {
    asm volatile("ldmatrix.sync.aligned.m8n8.x4.shared.b16 {%0,%1,%2,%3}, [%4];"
                 : "=r"(r[0]), "=r"(r[1]), "=r"(r[2]), "=r"(r[3]) : "r"(a));
}
__device__ __forceinline__ void ldm_x4_t(uint32_t* r, uint32_t a) {
    asm volatile("ldmatrix.sync.aligned.m8n8.x4.trans.shared.b16 {%0,%1,%2,%3}, [%4];"
                 : "=r"(r[0]), "=r"(r[1]), "=r"(r[2]), "=r"(r[3]) : "r"(a));
}
__device__ __forceinline__ void mma16816(float* c, const uint32_t* a, uint32_t b0, uint32_t b1) {
    asm volatile("mma.sync.aligned.m16n8k16.row.col.f32.f16.f16.f32 "
                 "{%0,%1,%2,%3}, {%4,%5,%6,%7}, {%8,%9}, {%0,%1,%2,%3};"
                 : "+f"(c[0]), "+f"(c[1]), "+f"(c[2]), "+f"(c[3])
                 : "r"(a[0]), "r"(a[1]), "r"(a[2]), "r"(a[3]), "r"(b0), "r"(b1));
}
#define CP16(dst, src) \
    asm volatile("cp.async.cg.shared.global [%0], [%1], 16;" :: "r"(dst), "l"(src) : "memory")
#define CP16Z(dst, src, n) \
    asm volatile("cp.async.cg.shared.global [%0], [%1], 16, %2;" :: "r"(dst), "l"(src), "r"(n) : "memory")
#define CP_COMMIT() asm volatile("cp.async.commit_group;" ::: "memory")
#define CP_WAIT1()  asm volatile("cp.async.wait_group 1;" ::: "memory")
#define CP_WAIT0()  asm volatile("cp.async.wait_group 0;" ::: "memory")

__device__ __forceinline__ float gelu_tanh(float gv) {
    float t  = gv + 0.044715f * gv * gv * gv;
    float z  = 1.5957691216057308f * t;
    float th = 1.0f - 2.0f / (__expf(z) + 1.0f);
    return 0.5f * gv * (1.0f + th);
}
__device__ __forceinline__ uint32_t pkh(__half a, __half b) {
    __half2 t = __halves2half2(a, b);
    return *reinterpret_cast<uint32_t*>(&t);
}

// ============================ prep kernels ============================
__global__ void k_zero_counts() { if (threadIdx.x < NE) g_cnt[threadIdx.x] = 0; }

__global__ void k_route(const int* __restrict__ sel) {
    int p = blockIdx.x * blockDim.x + threadIdx.x;
    if (p < MAXP) {
        int e = sel[p];
        int pos = atomicAdd(&g_cnt[e], 1);
        g_pair[e * MAXP + pos] = p;
    }
}

__global__ void k_half4(const float* __restrict__ src, __half* __restrict__ dst, int n4) {
    int i = blockIdx.x * blockDim.x + threadIdx.x;
    if (i >= n4) return;
    float4 v = ((const float4*)src)[i];
    __half2 a = __floats2half2_rn(v.x, v.y);
    __half2 b = __floats2half2_rn(v.z, v.w);
    ((uint2*)dst)[i] = make_uint2(*(uint32_t*)&a, *(uint32_t*)&b);
}

__global__ void k_split4(const float* __restrict__ src,
                         __half* __restrict__ dh, __half* __restrict__ dl, int n4) {
    int i = blockIdx.x * blockDim.x + threadIdx.x;
    if (i >= n4) return;
    float4 v = ((const float4*)src)[i];
    __half h0 = __float2half_rn(v.x), h1 = __float2half_rn(v.y);
    __half h2 = __float2half_rn(v.z), h3 = __float2half_rn(v.w);
    __half l0 = __float2half_rn(v.x - __half2float(h0));
    __half l1 = __float2half_rn(v.y - __half2float(h1));
    __half l2 = __float2half_rn(v.z - __half2float(h2));
    __half l3 = __float2half_rn(v.w - __half2float(h3));
    ((uint2*)dh)[i] = make_uint2(pkh(h0, h1), pkh(h2, h3));
    ((uint2*)dl)[i] = make_uint2(pkh(l0, l1), pkh(l2, l3));
}

// ============================ issue helpers ============================
__device__ __forceinline__ void gu_issue(int ck, int st, uint32_t sbd, const int* sPair,
                                         const __half* gw, const __half* uw,
                                         int cb, int tid)
{
    uint32_t sbase = sbd + st * STAGE;
    #pragma unroll
    for (int it = 0; it < 2; ++it) {
        int s = tid + it * 512;
        int hl = s >> 9, rem = s & 511;
        int r = rem >> 2, c = rem & 3;
        int pr = sPair[r];
        const __half* src = (hl ? g_x_l : g_x_h)
                          + ((size_t)((pr >= 0) ? (pr >> 1) : 0) * HD + ck * 32 + c * 8);
        uint32_t dst = sbase + hl * ABYTES + (uint32_t)(r * SAW + c * 8) * 2;
        CP16Z(dst, src, (pr >= 0) ? 16u : 0u);
    }
    {
        int r = tid >> 4, c = tid & 15;           // c: 0..7 gate, 8..15 up
        const __half* w = (c < 8) ? gw : uw;
        const __half* src = w + (size_t)(ck * 32 + r) * ID + cb * 64 + (c & 7) * 8;
        uint32_t dst = sbase + BOFF + (uint32_t)(r * SBW + c * 8) * 2;
        CP16(dst, src);
    }
    CP_COMMIT();
}

__device__ __forceinline__ void dn_issue(int ck, int st, uint32_t sbd, const int* sPair,
                                         const __half* dw, int cb, int tid)
{
    uint32_t sbase = sbd + st * STAGE;
    #pragma unroll
    for (int it = 0; it < 2; ++it) {
        int s = tid + it * 512;
        int hl = s >> 9, rem = s & 511;
        int r = rem >> 2, c = rem & 3;
        int pr = sPair[r];
        const __half* src = (hl ? g_act_l : g_act_h)
                          + ((size_t)((pr >= 0) ? pr : 0) * ID + ck * 32 + c * 8);
        uint32_t dst = sbase + hl * ABYTES + (uint32_t)(r * SAW + c * 8) * 2;
        CP16Z(dst, src, (pr >= 0) ? 16u : 0u);
    }
    {
        int r = tid >> 4, c = tid & 15;
        const __half* src = dw + (size_t)(ck * 32 + r) * HD + cb * 128 + c * 8;
        uint32_t dst = sbase + BOFF + (uint32_t)(r * SBW + c * 8) * 2;
        CP16(dst, src);
    }
    CP_COMMIT();
}

// ============================ gate+up ============================
// CTA: 128 pairs x (64 gate + 64 up cols), K=HD, 32-chunks, 3-stage, 2 CTA/SM.
__global__ __launch_bounds__(512, 2)
void k_gateup(const float* __restrict__ rw)
{
    const int e = blockIdx.z;
    const int cnt = g_cnt[e];
    const int row0 = blockIdx.y * 128;
    if (row0 >= cnt) return;
    const int cb = blockIdx.x;

    extern __shared__ char smem[];
    __shared__ int sPair[128];
    const uint32_t sbd = smem_to_u32(smem);
    const int tid = threadIdx.x, wid = tid >> 5, lane = tid & 31;
    const int wm = wid >> 2, wn = wid & 3;

    if (tid < 128) {
        int pos = row0 + tid;
        sPair[tid] = (pos < cnt) ? g_pair[e * MAXP + pos] : -1;
    }
    __syncthreads();

    const __half* gw = g_gw + (size_t)e * HD * ID;
    const __half* uw = g_uw + (size_t)e * HD * ID;

    float acc[2][2][2][4];
    #pragma unroll
    for (int i = 0; i < 2; ++i)
        #pragma unroll
        for (int j = 0; j < 2; ++j)
            #pragma unroll
            for (int s = 0; s < 2; ++s)
                #pragma unroll
                for (int q = 0; q < 4; ++q) acc[i][j][s][q] = 0.f;

    gu_issue(0, 0, sbd, sPair, gw, uw, cb, tid);
    gu_issue(1, 1, sbd, sPair, gw, uw, cb, tid);

    const int NCK = HD / 32;
    for (int ck = 0; ck < NCK; ++ck) {
        if (ck < NCK - 1) CP_WAIT1(); else CP_WAIT0();
        __syncthreads();

        const int st = ck % 3;
        uint32_t uA = sbd + st * STAGE;
        uint32_t uB = uA + BOFF;
        #pragma unroll
        for (int ks = 0; ks < 2; ++ks) {
            uint32_t b[8];
            uint32_t brow = (uint32_t)(ks * 16 + (lane & 15));
            uint32_t co   = (uint32_t)((lane >> 4) << 3);
            ldm_x4_t(b,     uB + (brow * SBW + wn * 16 + co) * 2);
            ldm_x4_t(b + 4, uB + (brow * SBW + 64 + wn * 16 + co) * 2);
            #pragma unroll
            for (int mt = 0; mt < 2; ++mt) {
                uint32_t a[4];
                uint32_t off = (uint32_t)((wm * 32 + mt * 16 + (lane & 15)) * SAW
                                          + ks * 16 + co) * 2;
                ldm_x4(a, uA + off);
                mma16816(acc[mt][0][0], a, b[0], b[1]);
                mma16816(acc[mt][0][1], a, b[2], b[3]);
                mma16816(acc[mt][1][0], a, b[4], b[5]);
                mma16816(acc[mt][1][1], a, b[6], b[7]);
                ldm_x4(a, uA + ABYTES + off);
                mma16816(acc[mt][0][0], a, b[0], b[1]);
                mma16816(acc[mt][0][1], a, b[2], b[3]);
                mma16816(acc[mt][1][0], a, b[4], b[5]);
                mma16816(acc[mt][1][1], a, b[6], b[7]);
            }
        }
        if (ck + 2 < NCK) gu_issue(ck + 2, (ck + 2) % 3, sbd, sPair, gw, uw, cb, tid);
    }

    // epilogue: act = rw * gelu(gate) * up -> fp16 hi/lo scratch
    #pragma unroll
    for (int mt = 0; mt < 2; ++mt)
        #pragma unroll
        for (int s = 0; s < 2; ++s) {
            int c = cb * 64 + wn * 16 + s * 8 + (lane & 3) * 2;
            #pragma unroll
            for (int half = 0; half < 2; ++half) {
                int r = wm * 32 + mt * 16 + (lane >> 2) + half * 8;
                int pr = sPair[r];
                if (pr < 0) continue;
                float wgt = rw[pr];
                float g0 = acc[mt][0][s][half * 2], g1 = acc[mt][0][s][half * 2 + 1];
                float u0 = acc[mt][1][s][half * 2], u1 = acc[mt][1][s][half * 2 + 1];
                float o0 = wgt * gelu_tanh(g0) * u0;
                float o1 = wgt * gelu_tanh(g1) * u1;
                __half h0 = __float2half_rn(o0), h1 = __float2half_rn(o1);
                __half l0 = __float2half_rn(o0 - __half2float(h0));
                __half l1 = __float2half_rn(o1 - __half2float(h1));
                size_t base = (size_t)pr * ID + c;
                *(uint32_t*)(g_act_h + base) = pkh(h0, h1);
                *(uint32_t*)(g_act_l + base) = pkh(l0, l1);
            }
        }
}

// ============================ down ============================
// CTA: 128 pairs x 128 hidden cols, K=ID, 32-chunks, 3-stage, 2 CTA/SM.
__global__ __launch_bounds__(512, 2)
void k_down()
{
    const int e = blockIdx.z;
    const int cnt = g_cnt[e];
    const int row0 = blockIdx.y * 128;
    if (row0 >= cnt) return;
    const int cb = blockIdx.x;

    extern __shared__ char smem[];
    __shared__ int sPair[128];
    const uint32_t sbd = smem_to_u32(smem);
    const int tid = threadIdx.x, wid = tid >> 5, lane = tid & 31;
    const int wm = wid >> 2, wn = wid & 3;

    if (tid < 128) {
        int pos = row0 + tid;
        sPair[tid] = (pos < cnt) ? g_pair[e * MAXP + pos] : -1;
    }
    __syncthreads();

    const __half* dw = g_dw + (size_t)e * ID * HD;

    float acc[2][4][4];
    #pragma unroll
    for (int i = 0; i < 2; ++i)
        #pragma unroll
        for (int j = 0; j < 4; ++j)
            #pragma unroll
            for (int q = 0; q < 4; ++q) acc[i][j][q] = 0.f;

    dn_issue(0, 0, sbd, sPair, dw, cb, tid);
    dn_issue(1, 1, sbd, sPair, dw, cb, tid);

    const int NCK = ID / 32;
    for (int ck = 0; ck < NCK; ++ck) {
        if (ck < NCK - 1) CP_WAIT1(); else CP_WAIT0();
        __syncthreads();

        const int st = ck % 3;
        uint32_t uA = sbd + st * STAGE;
        uint32_t uB = uA + BOFF;
        #pragma unroll
        for (int ks = 0; ks < 2; ++ks) {
            uint32_t b[8];
            uint32_t brow = (uint32_t)(ks * 16 + (lane & 15));
            uint32_t co   = (uint32_t)((lane >> 4) << 3);
            ldm_x4_t(b,     uB + (brow * SBW + wn * 32 + co) * 2);
            ldm_x4_t(b + 4, uB + (brow * SBW + wn * 32 + 16 + co) * 2);
            #pragma unroll
            for (int mt = 0; mt < 2; ++mt) {
                uint32_t a[4];
                uint32_t off = (uint32_t)((wm * 32 + mt * 16 + (lane & 15)) * SAW
                                          + ks * 16 + co) * 2;
                ldm_x4(a, uA + off);
                mma16816(acc[mt][0], a, b[0], b[1]);
                mma16816(acc[mt][1], a, b[2], b[3]);
                mma16816(acc[mt][2], a, b[4], b[5]);
                mma16816(acc[mt][3], a, b[6], b[7]);
                ldm_x4(a, uA + ABYTES + off);
                mma16816(acc[mt][0], a, b[0], b[1]);
                mma16816(acc[mt][1], a, b[2], b[3]);
                mma16816(acc[mt][2], a, b[4], b[5]);
                mma16816(acc[mt][3], a, b[6], b[7]);
            }
        }
        if (ck + 2 < NCK) dn_issue(ck + 2, (ck + 2) % 3, sbd, sPair, dw, cb, tid);
    }

    // epilogue: per-pair fp32 scratch
    #pragma unroll
    for (int mt = 0; mt < 2; ++mt)
        #pragma unroll
        for (int j = 0; j < 4; ++j) {
            int c = cb * 128 + wn * 32 + j * 8 + (lane & 3) * 2;
            #pragma unroll
            for (int half = 0; half < 2; ++half) {
                int r = wm * 32 + mt * 16 + (lane >> 2) + half * 8;
                int pr = sPair[r];
                if (pr < 0) continue;
                float2 v = make_float2(acc[mt][j][half * 2], acc[mt][j][half * 2 + 1]);
                *(float2*)(g_ds + (size_t)pr * HD + c) = v;
            }
        }
}

// ============================ combine ============================
__global__ void k_combine(float* __restrict__ out) {
    int idx = blockIdx.x * blockDim.x + threadIdx.x;
    int t  = idx >> 9;
    int c4 = idx & 511;
    const float4* s4 = (const float4*)g_ds;
    float4 a = s4[(size_t)(2 * t) * 512 + c4];
    float4 b = s4[(size_t)(2 * t + 1) * 512 + c4];
    ((float4*)out)[idx] = make_float4(a.x + b.x, a.y + b.y, a.z + b.z, a.w + b.w);
}

// ============================ host ============================
extern "C" void kernel_launch(void* const* d_in, const int* in_sizes, int n_in,
                              void* d_out, int out_size)
{
    const float* x      = (const float*)d_in[0];
    const int*   sel    = (const int*)  d_in[1];
    const float* rw     = (const float*)d_in[2];
    const float* gate_w = (const float*)d_in[3];
    const float* up_w   = (const float*)d_in[4];
    const float* down_w = (const float*)d_in[5];
    float* out = (float*)d_out;

    cudaFuncSetAttribute(k_gateup, cudaFuncAttributeMaxDynamicSharedMemorySize, SMEM_SZ);
    cudaFuncSetAttribute(k_down,   cudaFuncAttributeMaxDynamicSharedMemorySize, SMEM_SZ);

    k_zero_counts<<<1, 32>>>();
    k_route<<<MAXP / 256, 256>>>(sel);

    {
        __half *xh, *xl, *gw, *uw, *dww;
        cudaGetSymbolAddress((void**)&xh,  g_x_h);
        cudaGetSymbolAddress((void**)&xl,  g_x_l);
        cudaGetSymbolAddress((void**)&gw,  g_gw);
        cudaGetSymbolAddress((void**)&uw,  g_uw);
        cudaGetSymbolAddress((void**)&dww, g_dw);
        int nx4 = NT * HD / 4;
        int nw4 = NE * HD * ID / 4;
        k_split4<<<(nx4 + 255) / 256, 256>>>(x, xh, xl, nx4);
        k_half4<<<(nw4 + 255) / 256, 256>>>(gate_w, gw, nw4);
        k_half4<<<(nw4 + 255) / 256, 256>>>(up_w,   uw, nw4);
        k_half4<<<(nw4 + 255) / 256, 256>>>(down_w, dww, nw4);
    }

    dim3 g1(ID / 64, MAXP / 128, NE);    // 16 x 128 x 8
    k_gateup<<<g1, 512, SMEM_SZ>>>(rw);

    dim3 g2(HD / 128, MAXP / 128, NE);   // 16 x 128 x 8
    k_down<<<g2, 512, SMEM_SZ>>>();

    k_combine<<<(NT * HD / 4) / 256, 256>>>(out);
}

// round 12
// speedup vs baseline: 2.3381x; 1.2954x over previous
#include <cuda_runtime.h>
#include <cuda_fp16.h>
#include <cstdint>
#include <math.h>

#define NE   8
#define HD   2048
#define ID   1024
#define NT   8192
#define TOPK 2
#define MAXP (NT * TOPK)

// smem geometry (fp16 elems)
#define SAW    40                    // A row stride: 32 data + 8 pad (80 B)
#define SBW    136                   // B row stride: 128 data + 8 pad (272 B)
#define ABYTES (128 * SAW * 2)       // 10240
#define BBYTES (32 * SBW * 2)        // 8704

// gateup: A single-term
#define GU_BOFF   ABYTES             // 10240
#define GU_STAGE  (GU_BOFF + BBYTES) // 18944
#define GU_SMEM   (3 * GU_STAGE)     // 56832

// down: A hi+lo
#define DN_BOFF   (2 * ABYTES)       // 20480
#define DN_STAGE  (DN_BOFF + BBYTES) // 29184
#define DN_SMEM   (3 * DN_STAGE)     // 87552

// ---- device globals ----
__device__ int    g_cnt[NE];
__device__ int    g_pair[NE * MAXP];
__device__ __half g_x_h[(size_t)NT * HD];
__device__ __half g_gw[(size_t)NE * HD * ID];
__device__ __half g_uw[(size_t)NE * HD * ID];
__device__ __half g_dw[(size_t)NE * ID * HD];
__device__ __half g_act_h[(size_t)MAXP * ID];
__device__ __half g_act_l[(size_t)MAXP * ID];
__device__ float  g_ds[(size_t)MAXP * HD];

// ============================ asm helpers ============================
__device__ __forceinline__ uint32_t smem_to_u32(const void* p) {
    uint32_t a;
    asm("{ .reg .u64 t; cvta.to.shared.u64 t, %1; cvt.u32.u64 %0, t; }" : "=r"(a) : "l"(p));
    return a;
}
__device__ __forceinline__ void ldm_x4(uint32_t* r, uint32_t a) {
    asm volatile("ldmatrix.sync.aligned.m8n8.x4.shared.b16 {%0,%1,%2,%3}, [%4];"
                 : "=r"(r[0]), "=r"(r[1]), "=r"(r[2]), "=r"(r[3]) : "r"(a));
}
__device__ __forceinline__ void ldm_x4_t(uint32_t* r, uint32_t a) {
    asm volatile("ldmatrix.sync.aligned.m8n8.x4.trans.shared.b16 {%0,%1,%2,%3}, [%4];"
                 : "=r"(r[0]), "=r"(r[1]), "=r"(r[2]), "=r"(r[3]) : "r"(a));
}
__device__ __forceinline__ void mma16816(float* c, const uint32_t* a, uint32_t b0, uint32_t b1) {
    asm volatile("mma.sync.aligned.m16n8k16.row.col.f32.f16.f16.f32 "
                 "{%0,%1,%2,%3}, {%4,%5,%6,%7}, {%8,%9}, {%0,%1,%2,%3};"
                 : "+f"(c[0]), "+f"(c[1]), "+f"(c[2]), "+f"(c[3])
                 : "r"(a[0]), "r"(a[1]), "r"(a[2]), "r"(a[3]), "r"(b0), "r"(b1));
}
#define CP16(dst, src) \
    asm volatile("cp.async.cg.shared.global [%0], [%1], 16;" :: "r"(dst), "l"(src) : "memory")
#define CP16Z(dst, src, n) \
    asm volatile("cp.async.cg.shared.global [%0], [%1], 16, %2;" :: "r"(dst), "l"(src), "r"(n) : "memory")
#define CP_COMMIT() asm volatile("cp.async.commit_group;" ::: "memory")
#define CP_WAIT1()  asm volatile("cp.async.wait_group 1;" ::: "memory")
#define CP_WAIT0()  asm volatile("cp.async.wait_group 0;" ::: "memory")

__device__ __forceinline__ float gelu_tanh(float gv) {
    float t  = gv + 0.044715f * gv * gv * gv;
    float z  = 1.5957691216057308f * t;
    float th = 1.0f - 2.0f / (__expf(z) + 1.0f);
    return 0.5f * gv * (1.0f + th);
}
__device__ __forceinline__ uint32_t pkh(__half a, __half b) {
    __half2 t = __halves2half2(a, b);
    return *reinterpret_cast<uint32_t*>(&t);
}

// ============================ prep kernels ============================
__global__ void k_zero_counts() { if (threadIdx.x < NE) g_cnt[threadIdx.x] = 0; }

__global__ void k_route(const int* __restrict__ sel) {
    int p = blockIdx.x * blockDim.x + threadIdx.x;
    if (p < MAXP) {
        int e = sel[p];
        int pos = atomicAdd(&g_cnt[e], 1);
        g_pair[e * MAXP + pos] = p;
    }
}

__global__ void k_half4(const float* __restrict__ src, __half* __restrict__ dst, int n4) {
    int i = blockIdx.x * blockDim.x + threadIdx.x;
    if (i >= n4) return;
    float4 v = ((const float4*)src)[i];
    __half2 a = __floats2half2_rn(v.x, v.y);
    __half2 b = __floats2half2_rn(v.z, v.w);
    ((uint2*)dst)[i] = make_uint2(*(uint32_t*)&a, *(uint32_t*)&b);
}

// ============================ issue helpers ============================
// gateup: A 128x32 single fp16 (1 cp/thread), B 32x128 (1 cp/thread)
__device__ __forceinline__ void gu_issue(int ck, int st, uint32_t sbd, const int* sPair,
                                         const __half* gw, const __half* uw,
                                         int cb, int tid)
{
    uint32_t sbase = sbd + st * GU_STAGE;
    {
        int r = tid >> 2, c = tid & 3;
        int pr = sPair[r];
        const __half* src = g_x_h
                          + ((size_t)((pr >= 0) ? (pr >> 1) : 0) * HD + ck * 32 + c * 8);
        uint32_t dst = sbase + (uint32_t)(r * SAW + c * 8) * 2;
        CP16Z(dst, src, (pr >= 0) ? 16u : 0u);
    }
    {
        int r = tid >> 4, c = tid & 15;           // c: 0..7 gate, 8..15 up
        const __half* w = (c < 8) ? gw : uw;
        const __half* src = w + (size_t)(ck * 32 + r) * ID + cb * 64 + (c & 7) * 8;
        uint32_t dst = sbase + GU_BOFF + (uint32_t)(r * SBW + c * 8) * 2;
        CP16(dst, src);
    }
    CP_COMMIT();
}

// down: A 128x32 hi+lo (2 cp/thread), B 32x128 (1 cp/thread)
__device__ __forceinline__ void dn_issue(int ck, int st, uint32_t sbd, const int* sPair,
                                         const __half* dw, int cb, int tid)
{
    uint32_t sbase = sbd + st * DN_STAGE;
    #pragma unroll
    for (int it = 0; it < 2; ++it) {
        int s = tid + it * 512;
        int hl = s >> 9, rem = s & 511;
        int r = rem >> 2, c = rem & 3;
        int pr = sPair[r];
        const __half* src = (hl ? g_act_l : g_act_h)
                          + ((size_t)((pr >= 0) ? pr : 0) * ID + ck * 32 + c * 8);
        uint32_t dst = sbase + hl * ABYTES + (uint32_t)(r * SAW + c * 8) * 2;
        CP16Z(dst, src, (pr >= 0) ? 16u : 0u);
    }
    {
        int r = tid >> 4, c = tid & 15;
        const __half* src = dw + (size_t)(ck * 32 + r) * HD + cb * 128 + c * 8;
        uint32_t dst = sbase + DN_BOFF + (uint32_t)(r * SBW + c * 8) * 2;
        CP16(dst, src);
    }
    CP_COMMIT();
}

// ============================ gate+up ============================
// CTA: 128 pairs x (64 gate + 64 up cols), K=HD, 32-chunks, 3-stage, 2 CTA/SM.
// A single-term fp16 (B fp16 rounding dominates error; A-lo dropped).
__global__ __launch_bounds__(512, 2)
void k_gateup(const float* __restrict__ rw)
{
    const int e = blockIdx.z;
    const int cnt = g_cnt[e];
    const int row0 = blockIdx.y * 128;
    if (row0 >= cnt) return;
    const int cb = blockIdx.x;

    extern __shared__ char smem[];
    __shared__ int sPair[128];
    const uint32_t sbd = smem_to_u32(smem);
    const int tid = threadIdx.x, wid = tid >> 5, lane = tid & 31;
    const int wm = wid >> 2, wn = wid & 3;

    if (tid < 128) {
        int pos = row0 + tid;
        sPair[tid] = (pos < cnt) ? g_pair[e * MAXP + pos] : -1;
    }
    __syncthreads();

    const __half* gw = g_gw + (size_t)e * HD * ID;
    const __half* uw = g_uw + (size_t)e * HD * ID;

    float acc[2][2][2][4];
    #pragma unroll
    for (int i = 0; i < 2; ++i)
        #pragma unroll
        for (int j = 0; j < 2; ++j)
            #pragma unroll
            for (int s = 0; s < 2; ++s)
                #pragma unroll
                for (int q = 0; q < 4; ++q) acc[i][j][s][q] = 0.f;

    gu_issue(0, 0, sbd, sPair, gw, uw, cb, tid);
    gu_issue(1, 1, sbd, sPair, gw, uw, cb, tid);

    const int NCK = HD / 32;
    for (int ck = 0; ck < NCK; ++ck) {
        if (ck < NCK - 1) CP_WAIT1(); else CP_WAIT0();
        __syncthreads();

        const int st = ck % 3;
        uint32_t uA = sbd + st * GU_STAGE;
        uint32_t uB = uA + GU_BOFF;
        #pragma unroll
        for (int ks = 0; ks < 2; ++ks) {
            uint32_t b[8];
            uint32_t brow = (uint32_t)(ks * 16 + (lane & 15));
            uint32_t co   = (uint32_t)((lane >> 4) << 3);
            ldm_x4_t(b,     uB + (brow * SBW + wn * 16 + co) * 2);
            ldm_x4_t(b + 4, uB + (brow * SBW + 64 + wn * 16 + co) * 2);
            #pragma unroll
            for (int mt = 0; mt < 2; ++mt) {
                uint32_t a[4];
                uint32_t off = (uint32_t)((wm * 32 + mt * 16 + (lane & 15)) * SAW
                                          + ks * 16 + co) * 2;
                ldm_x4(a, uA + off);
                mma16816(acc[mt][0][0], a, b[0], b[1]);
                mma16816(acc[mt][0][1], a, b[2], b[3]);
                mma16816(acc[mt][1][0], a, b[4], b[5]);
                mma16816(acc[mt][1][1], a, b[6], b[7]);
            }
        }
        if (ck + 2 < NCK) gu_issue(ck + 2, (ck + 2) % 3, sbd, sPair, gw, uw, cb, tid);
    }

    // epilogue: act = rw * gelu(gate) * up -> fp16 hi/lo scratch
    #pragma unroll
    for (int mt = 0; mt < 2; ++mt)
        #pragma unroll
        for (int s = 0; s < 2; ++s) {
            int c = cb * 64 + wn * 16 + s * 8 + (lane & 3) * 2;
            #pragma unroll
            for (int half = 0; half < 2; ++half) {
                int r = wm * 32 + mt * 16 + (lane >> 2) + half * 8;
                int pr = sPair[r];
                if (pr < 0) continue;
                float wgt = rw[pr];
                float g0 = acc[mt][0][s][half * 2], g1 = acc[mt][0][s][half * 2 + 1];
                float u0 = acc[mt][1][s][half * 2], u1 = acc[mt][1][s][half * 2 + 1];
                float o0 = wgt * gelu_tanh(g0) * u0;
                float o1 = wgt * gelu_tanh(g1) * u1;
                __half h0 = __float2half_rn(o0), h1 = __float2half_rn(o1);
                __half l0 = __float2half_rn(o0 - __half2float(h0));
                __half l1 = __float2half_rn(o1 - __half2float(h1));
                size_t base = (size_t)pr * ID + c;
                *(uint32_t*)(g_act_h + base) = pkh(h0, h1);
                *(uint32_t*)(g_act_l + base) = pkh(l0, l1);
            }
        }
}

// ============================ down ============================
// CTA: 128 pairs x 128 hidden cols, K=ID, 32-chunks, 3-stage, 2 CTA/SM.
// A = act hi/lo (2-term), B single fp16.
__global__ __launch_bounds__(512, 2)
void k_down()
{
    const int e = blockIdx.z;
    const int cnt = g_cnt[e];
    const int row0 = blockIdx.y * 128;
    if (row0 >= cnt) return;
    const int cb = blockIdx.x;

    extern __shared__ char smem[];
    __shared__ int sPair[128];
    const uint32_t sbd = smem_to_u32(smem);
    const int tid = threadIdx.x, wid = tid >> 5, lane = tid & 31;
    const int wm = wid >> 2, wn = wid & 3;

    if (tid < 128) {
        int pos = row0 + tid;
        sPair[tid] = (pos < cnt) ? g_pair[e * MAXP + pos] : -1;
    }
    __syncthreads();

    const __half* dw = g_dw + (size_t)e * ID * HD;

    float acc[2][4][4];
    #pragma unroll
    for (int i = 0; i < 2; ++i)
        #pragma unroll
        for (int j = 0; j < 4; ++j)
            #pragma unroll
            for (int q = 0; q < 4; ++q) acc[i][j][q] = 0.f;

    dn_issue(0, 0, sbd, sPair, dw, cb, tid);
    dn_issue(1, 1, sbd, sPair, dw, cb, tid);

    const int NCK = ID / 32;
    for (int ck = 0; ck < NCK; ++ck) {
        if (ck < NCK - 1) CP_WAIT1(); else CP_WAIT0();
        __syncthreads();

        const int st = ck % 3;
        uint32_t uA = sbd + st * DN_STAGE;
        uint32_t uB = uA + DN_BOFF;
        #pragma unroll
        for (int ks = 0; ks < 2; ++ks) {
            uint32_t b[8];
            uint32_t brow = (uint32_t)(ks * 16 + (lane & 15));
            uint32_t co   = (uint32_t)((lane >> 4) << 3);
            ldm_x4_t(b,     uB + (brow * SBW + wn * 32 + co) * 2);
            ldm_x4_t(b + 4, uB + (brow * SBW + wn * 32 + 16 + co) * 2);
            #pragma unroll
            for (int mt = 0; mt < 2; ++mt) {
                uint32_t a[4];
                uint32_t off = (uint32_t)((wm * 32 + mt * 16 + (lane & 15)) * SAW
                                          + ks * 16 + co) * 2;
                ldm_x4(a, uA + off);
                mma16816(acc[mt][0], a, b[0], b[1]);
                mma16816(acc[mt][1], a, b[2], b[3]);
                mma16816(acc[mt][2], a, b[4], b[5]);
                mma16816(acc[mt][3], a, b[6], b[7]);
                ldm_x4(a, uA + ABYTES + off);
                mma16816(acc[mt][0], a, b[0], b[1]);
                mma16816(acc[mt][1], a, b[2], b[3]);
                mma16816(acc[mt][2], a, b[4], b[5]);
                mma16816(acc[mt][3], a, b[6], b[7]);
            }
        }
        if (ck + 2 < NCK) dn_issue(ck + 2, (ck + 2) % 3, sbd, sPair, dw, cb, tid);
    }

    // epilogue: per-pair fp32 scratch
    #pragma unroll
    for (int mt = 0; mt < 2; ++mt)
        #pragma unroll
        for (int j = 0; j < 4; ++j) {
            int c = cb * 128 + wn * 32 + j * 8 + (lane & 3) * 2;
            #pragma unroll
            for (int half = 0; half < 2; ++half) {
                int r = wm * 32 + mt * 16 + (lane >> 2) + half * 8;
                int pr = sPair[r];
                if (pr < 0) continue;
                float2 v = make_float2(acc[mt][j][half * 2], acc[mt][j][half * 2 + 1]);
                *(float2*)(g_ds + (size_t)pr * HD + c) = v;
            }
        }
}

// ============================ combine ============================
__global__ void k_combine(float* __restrict__ out) {
    int idx = blockIdx.x * blockDim.x + threadIdx.x;
    int t  = idx >> 9;
    int c4 = idx & 511;
    const float4* s4 = (const float4*)g_ds;
    float4 a = s4[(size_t)(2 * t) * 512 + c4];
    float4 b = s4[(size_t)(2 * t + 1) * 512 + c4];
    ((float4*)out)[idx] = make_float4(a.x + b.x, a.y + b.y, a.z + b.z, a.w + b.w);
}

// ============================ host ============================
extern "C" void kernel_launch(void* const* d_in, const int* in_sizes, int n_in,
                              void* d_out, int out_size)
{
    const float* x      = (const float*)d_in[0];
    const int*   sel    = (const int*)  d_in[1];
    const float* rw     = (const float*)d_in[2];
    const float* gate_w = (const float*)d_in[3];
    const float* up_w   = (const float*)d_in[4];
    const float* down_w = (const float*)d_in[5];
    float* out = (float*)d_out;

    cudaFuncSetAttribute(k_gateup, cudaFuncAttributeMaxDynamicSharedMemorySize, GU_SMEM);
    cudaFuncSetAttribute(k_down,   cudaFuncAttributeMaxDynamicSharedMemorySize, DN_SMEM);

    k_zero_counts<<<1, 32>>>();
    k_route<<<MAXP / 256, 256>>>(sel);

    {
        __half *xh, *gw, *uw, *dww;
        cudaGetSymbolAddress((void**)&xh,  g_x_h);
        cudaGetSymbolAddress((void**)&gw,  g_gw);
        cudaGetSymbolAddress((void**)&uw,  g_uw);
        cudaGetSymbolAddress((void**)&dww, g_dw);
        int nx4 = NT * HD / 4;
        int nw4 = NE * HD * ID / 4;
        k_half4<<<(nx4 + 255) / 256, 256>>>(x, xh, nx4);
        k_half4<<<(nw4 + 255) / 256, 256>>>(gate_w, gw, nw4);
        k_half4<<<(nw4 + 255) / 256, 256>>>(up_w,   uw, nw4);
        k_half4<<<(nw4 + 255) / 256, 256>>>(down_w, dww, nw4);
    }

    dim3 g1(ID / 64, MAXP / 128, NE);    // 16 x 128 x 8
    k_gateup<<<g1, 512, GU_SMEM>>>(rw);

    dim3 g2(HD / 128, MAXP / 128, NE);   // 16 x 128 x 8
    k_down<<<g2, 512, DN_SMEM>>>();

    k_combine<<<(NT * HD / 4) / 256, 256>>>(out);
}